// round 1
// baseline (speedup 1.0000x reference)
#include <cuda_runtime.h>

#define SEQ   2048
#define DM    768
#define BATCH 4
#define NH    12
#define HD    64
#define ROWS  (BATCH*SEQ)   /* 8192 */
#define ZBN   (BATCH*NH)    /* 48 */

// Scratch (device globals: allocation-free per harness rules)
__device__ float g_q[ROWS*DM];
__device__ float g_k[ROWS*DM];
__device__ float g_v[ROWS*DM];
__device__ float g_o[ROWS*DM];
__device__ float g_S[(long)ZBN*SEQ*SEQ];   // 805 MB
__device__ float g_cm[ZBN*SEQ];
__device__ float g_rs[ZBN*SEQ];

// ---------------------------------------------------------------------------
// Generic K-major SGEMM: C[m,n] = alpha * sum_k A[m,k]*B[n,k] (+bias[n]) (+resid[m,n])
// Optional batching over blockIdx.z with (batch, head) offset decomposition.
// Tile 128x128, BK=16, 256 threads, 8x8 per thread (columns split tx*4 / 64+tx*4).
// ---------------------------------------------------------------------------
__global__ __launch_bounds__(256) void sgemm_kt(
    const float* __restrict__ A, int lda, long sAb, long sAh,
    const float* __restrict__ B, int ldb, long sBb, long sBh,
    float* __restrict__ C, int ldc, long sC,
    int K, int heads, float alpha,
    const float* __restrict__ bias,
    const float* __restrict__ resid)
{
    __shared__ float As[16][132];
    __shared__ float Bs[16][132];

    const int t  = threadIdx.x;
    const int z  = blockIdx.z;
    const int zb = z / heads;
    const int zh = z - zb * heads;
    A += (long)zb * sAb + (long)zh * sAh;
    B += (long)zb * sBb + (long)zh * sBh;
    C += (long)z * sC;

    const int m0 = blockIdx.y << 7;
    const int n0 = blockIdx.x << 7;
    const int arow = t >> 2;
    const int acol = (t & 3) << 2;
    const int ty = t >> 4, tx = t & 15;

    float acc[8][8] = {};

    for (int k0 = 0; k0 < K; k0 += 16) {
#pragma unroll
        for (int i = 0; i < 2; i++) {
            const int r = arow + (i << 6);
            float4 va = *reinterpret_cast<const float4*>(A + (long)(m0 + r) * lda + k0 + acol);
            As[acol    ][r] = va.x;
            As[acol + 1][r] = va.y;
            As[acol + 2][r] = va.z;
            As[acol + 3][r] = va.w;
            float4 vb = *reinterpret_cast<const float4*>(B + (long)(n0 + r) * ldb + k0 + acol);
            Bs[acol    ][r] = vb.x;
            Bs[acol + 1][r] = vb.y;
            Bs[acol + 2][r] = vb.z;
            Bs[acol + 3][r] = vb.w;
        }
        __syncthreads();
#pragma unroll
        for (int kk = 0; kk < 16; kk++) {
            float4 a0 = *reinterpret_cast<const float4*>(&As[kk][ty * 8]);
            float4 a1 = *reinterpret_cast<const float4*>(&As[kk][ty * 8 + 4]);
            float4 b0 = *reinterpret_cast<const float4*>(&Bs[kk][tx * 4]);
            float4 b1 = *reinterpret_cast<const float4*>(&Bs[kk][64 + tx * 4]);
            float a[8] = {a0.x, a0.y, a0.z, a0.w, a1.x, a1.y, a1.z, a1.w};
            float b[8] = {b0.x, b0.y, b0.z, b0.w, b1.x, b1.y, b1.z, b1.w};
#pragma unroll
            for (int i = 0; i < 8; i++)
#pragma unroll
                for (int j = 0; j < 8; j++)
                    acc[i][j] += a[i] * b[j];
        }
        __syncthreads();
    }

#pragma unroll
    for (int i = 0; i < 8; i++) {
        const int m = m0 + ty * 8 + i;
#pragma unroll
        for (int g = 0; g < 2; g++) {
            const int n = n0 + (g << 6) + tx * 4;
            float4 v;
            v.x = acc[i][g * 4 + 0] * alpha;
            v.y = acc[i][g * 4 + 1] * alpha;
            v.z = acc[i][g * 4 + 2] * alpha;
            v.w = acc[i][g * 4 + 3] * alpha;
            if (bias) {
                float4 bf = *reinterpret_cast<const float4*>(bias + n);
                v.x += bf.x; v.y += bf.y; v.z += bf.z; v.w += bf.w;
            }
            if (resid) {
                float4 rf = *reinterpret_cast<const float4*>(resid + (long)m * ldc + n);
                v.x += rf.x; v.y += rf.y; v.z += rf.z; v.w += rf.w;
            }
            *reinterpret_cast<float4*>(C + (long)m * ldc + n) = v;
        }
    }
}

// ---------------------------------------------------------------------------
// Row LayerNorm (no bias), d = 768, in-place, 256 threads per row.
// ---------------------------------------------------------------------------
__global__ __launch_bounds__(256) void ln_kernel(float* __restrict__ xio,
                                                 const float* __restrict__ gamma)
{
    const long row = blockIdx.x;
    float* p = xio + row * DM;
    const int t = threadIdx.x;

    float v0 = p[t], v1 = p[t + 256], v2 = p[t + 512];
    float s  = v0 + v1 + v2;
    float sq = v0 * v0 + v1 * v1 + v2 * v2;

#pragma unroll
    for (int o = 16; o; o >>= 1) {
        s  += __shfl_xor_sync(0xffffffffu, s,  o);
        sq += __shfl_xor_sync(0xffffffffu, sq, o);
    }
    __shared__ float ss[8], sqs[8];
    const int w = t >> 5, ln = t & 31;
    if (ln == 0) { ss[w] = s; sqs[w] = sq; }
    __syncthreads();
    if (w == 0) {
        s  = (ln < 8) ? ss[ln]  : 0.f;
        sq = (ln < 8) ? sqs[ln] : 0.f;
#pragma unroll
        for (int o = 4; o; o >>= 1) {
            s  += __shfl_xor_sync(0xffffffffu, s,  o);
            sq += __shfl_xor_sync(0xffffffffu, sq, o);
        }
        if (ln == 0) { ss[0] = s; sqs[0] = sq; }
    }
    __syncthreads();
    const float mu   = ss[0] * (1.f / DM);
    const float var  = sqs[0] * (1.f / DM) - mu * mu;
    const float rstd = rsqrtf(var + 1e-5f);

    p[t]       = (v0 - mu) * rstd * gamma[t];
    p[t + 256] = (v1 - mu) * rstd * gamma[t + 256];
    p[t + 512] = (v2 - mu) * rstd * gamma[t + 512];
}

// ---------------------------------------------------------------------------
// Column stats for softmax over the QUERY axis: for each (z, k) column,
// max over q and 1/sum_q exp(S - max). Coalesced: thread <-> key column.
// ---------------------------------------------------------------------------
__global__ __launch_bounds__(256) void colstats_kernel(
    const float* __restrict__ S, float* __restrict__ cm, float* __restrict__ rs)
{
    const int z  = blockIdx.y;
    const int kc = (blockIdx.x << 8) + threadIdx.x;
    const float* p = S + (long)z * SEQ * SEQ + kc;

    float m = -1e30f;
    for (int q = 0; q < SEQ; q++) m = fmaxf(m, p[(long)q * SEQ]);
    float s = 0.f;
    for (int q = 0; q < SEQ; q++) s += __expf(p[(long)q * SEQ] - m);

    cm[z * SEQ + kc] = m;
    rs[z * SEQ + kc] = 1.0f / s;
}

// ---------------------------------------------------------------------------
// O = P @ V per (b,h), where P[q,k] = exp(S-colmax[k]) * rcolsum[k] is formed
// on the fly in the smem load. Tile: 128 q x 64 hd, BK=32 keys.
// Writes directly to merged (b, l, h*hd) layout.
// ---------------------------------------------------------------------------
__global__ __launch_bounds__(256) void pv_kernel(
    const float* __restrict__ S, const float* __restrict__ V,
    const float* __restrict__ cm, const float* __restrict__ rs,
    float* __restrict__ O)
{
    __shared__ float Ps[32][132];
    __shared__ float Vs[32][68];

    const int z = blockIdx.y;
    const int b = z / NH, h = z - b * NH;
    const int q0 = blockIdx.x << 7;
    const float* Sp  = S  + (long)z * SEQ * SEQ;
    const float* cmz = cm + z * SEQ;
    const float* rsz = rs + z * SEQ;
    const float* Vp  = V  + (long)b * SEQ * DM + h * HD;

    const int t  = threadIdx.x;
    const int ty = t >> 4, tx = t & 15;
    float acc[8][4] = {};

    for (int k0 = 0; k0 < SEQ; k0 += 32) {
#pragma unroll
        for (int i = 0; i < 4; i++) {
            const int idx = t + (i << 8);
            const int r = idx >> 3;
            const int c = (idx & 7) << 2;
            float4 sv = *reinterpret_cast<const float4*>(Sp + (long)(q0 + r) * SEQ + k0 + c);
            float4 m4 = *reinterpret_cast<const float4*>(cmz + k0 + c);
            float4 r4 = *reinterpret_cast<const float4*>(rsz + k0 + c);
            Ps[c    ][r] = __expf(sv.x - m4.x) * r4.x;
            Ps[c + 1][r] = __expf(sv.y - m4.y) * r4.y;
            Ps[c + 2][r] = __expf(sv.z - m4.z) * r4.z;
            Ps[c + 3][r] = __expf(sv.w - m4.w) * r4.w;
        }
#pragma unroll
        for (int i = 0; i < 2; i++) {
            const int idx = t + (i << 8);
            const int r = idx >> 4;
            const int c = (idx & 15) << 2;
            *reinterpret_cast<float4*>(&Vs[r][c]) =
                *reinterpret_cast<const float4*>(Vp + (long)(k0 + r) * DM + c);
        }
        __syncthreads();
#pragma unroll
        for (int kk = 0; kk < 32; kk++) {
            float4 a0 = *reinterpret_cast<const float4*>(&Ps[kk][ty * 8]);
            float4 a1 = *reinterpret_cast<const float4*>(&Ps[kk][ty * 8 + 4]);
            float4 bv = *reinterpret_cast<const float4*>(&Vs[kk][tx * 4]);
            float a[8] = {a0.x, a0.y, a0.z, a0.w, a1.x, a1.y, a1.z, a1.w};
#pragma unroll
            for (int i = 0; i < 8; i++) {
                acc[i][0] += a[i] * bv.x;
                acc[i][1] += a[i] * bv.y;
                acc[i][2] += a[i] * bv.z;
                acc[i][3] += a[i] * bv.w;
            }
        }
        __syncthreads();
    }

#pragma unroll
    for (int i = 0; i < 8; i++) {
        const long m = (long)(b * SEQ + q0 + ty * 8 + i);
        float4 v = {acc[i][0], acc[i][1], acc[i][2], acc[i][3]};
        *reinterpret_cast<float4*>(O + m * DM + h * HD + tx * 4) = v;
    }
}

// ---------------------------------------------------------------------------
extern "C" void kernel_launch(void* const* d_in, const int* in_sizes, int n_in,
                              void* d_out, int out_size)
{
    const float* x  = (const float*)d_in[0];
    const float* Wq = (const float*)d_in[1];
    const float* Wk = (const float*)d_in[2];
    const float* bk = (const float*)d_in[3];
    const float* Wv = (const float*)d_in[4];
    const float* bv = (const float*)d_in[5];
    const float* gq = (const float*)d_in[6];
    const float* gk = (const float*)d_in[7];
    const float* Wo = (const float*)d_in[8];
    const float* bo = (const float*)d_in[9];
    float* out = (float*)d_out;

    float *q, *k, *v, *o, *S, *cm, *rs;
    cudaGetSymbolAddress((void**)&q,  g_q);
    cudaGetSymbolAddress((void**)&k,  g_k);
    cudaGetSymbolAddress((void**)&v,  g_v);
    cudaGetSymbolAddress((void**)&o,  g_o);
    cudaGetSymbolAddress((void**)&S,  g_S);
    cudaGetSymbolAddress((void**)&cm, g_cm);
    cudaGetSymbolAddress((void**)&rs, g_rs);

    const dim3 blk(256);
    const dim3 gproj(DM / 128, ROWS / 128, 1);

    // Projections: q = x Wq^T, k = x Wk^T + bk, v = x Wv^T + bv
    sgemm_kt<<<gproj, blk>>>(x, DM, 0, 0, Wq, DM, 0, 0, q, DM, 0, DM, 1, 1.f, nullptr, nullptr);
    sgemm_kt<<<gproj, blk>>>(x, DM, 0, 0, Wk, DM, 0, 0, k, DM, 0, DM, 1, 1.f, bk,      nullptr);
    sgemm_kt<<<gproj, blk>>>(x, DM, 0, 0, Wv, DM, 0, 0, v, DM, 0, DM, 1, 1.f, bv,      nullptr);

    // QK-norm over full dmodel
    ln_kernel<<<ROWS, blk>>>(q, gq);
    ln_kernel<<<ROWS, blk>>>(k, gk);

    // Scores: S[z,q,k] = 0.125 * <q_head, k_head>, batched over z = b*12 + h
    const dim3 gs(SEQ / 128, SEQ / 128, ZBN);
    sgemm_kt<<<gs, blk>>>(q, DM, (long)SEQ * DM, HD,
                          k, DM, (long)SEQ * DM, HD,
                          S, SEQ, (long)SEQ * SEQ,
                          HD, NH, 0.125f, nullptr, nullptr);

    // Per-key-column softmax stats (softmax over query axis)
    colstats_kernel<<<dim3(SEQ / 256, ZBN), blk>>>(S, cm, rs);

    // O = softmax_q(S) @ V, merged-head layout
    pv_kernel<<<dim3(SEQ / 128, ZBN), blk>>>(S, v, cm, rs, o);

    // out = O @ Wo^T + bo + x
    sgemm_kt<<<gproj, blk>>>(o, DM, 0, 0, Wo, DM, 0, 0, out, DM, 0, DM, 1, 1.f, bo, x);
}